// round 14
// baseline (speedup 1.0000x reference)
#include <cuda_runtime.h>

// QAEEncoder R13: R12 (C2 pushed into measured operators, 3-way load,
// STS.128-paired T_B writes) + packed f32x2 final reductions.
// Layouts over amp index j[9:0] (qubit q <-> bit p=9-q):
//   L1: lane=j[9:5], reg=j[4:0]     L0: lane=j[4:0], reg r=j[9:5]
// Pipeline:
//   load+norm (L1, real, packed; norm folded into first gate)
//   -> A gates q9..5 (L1 regs, f32x2) -> T_A (L1->L0) -> A gates q4..0 (L0)
//   -> C1 gather+PhA (->L1 complex) -> B gates q9..5 (L1) -> T_B (L1->L0)
//   -> B gates q4..0 (L0) -> measure with (PhB . Perm)-conjugated operators;
//   stage-C RY folded; qubits 6-9 traced out.
// CNOT-ring: new[i]=old[g(i)], g(i)=(i^(i>>1))^((i&1)?0x300:0).
// Pushback (validated R10): Z_q -> Walsh masks; X_q/Y_q -> pair correlations
// at Delta_p = g(e_p) with 4 phase buckets from E_m = exp(i w[40+m]).
// Staging: T_A/C1 use float rows stride 34; T_B uses u64 rows stride 34
// (write pairs as STS.128: aligned for all lanes, conflict-free phases).

constexpr int SPB = 4;               // states (warps) per block
constexpr int NT  = 32 * SPB;
using u64 = unsigned long long;

__device__ float2 d_phA[1024];   // transposed: dest i at [(i&31)*32 + (i>>5)]
__device__ float2 d_g[33];       // [0,20)=gAB, [20,26)=gC, [26,33)=E_m=exp(i w[40+m])

__device__ __forceinline__ u64 pk2(float a, float b) {
    u64 r; asm("mov.b64 %0,{%1,%2};" : "=l"(r) : "f"(a), "f"(b)); return r;
}
__device__ __forceinline__ void upk2(u64 v, float& a, float& b) {
    asm("mov.b64 {%0,%1},%2;" : "=f"(a), "=f"(b) : "l"(v));
}
__device__ __forceinline__ u64 mul2(u64 a, u64 b) {
    u64 d; asm("mul.rn.f32x2 %0,%1,%2;" : "=l"(d) : "l"(a), "l"(b)); return d;
}
__device__ __forceinline__ u64 fma2(u64 a, u64 b, u64 c) {
    u64 d; asm("fma.rn.f32x2 %0,%1,%2,%3;" : "=l"(d) : "l"(a), "l"(b), "l"(c)); return d;
}
__device__ __forceinline__ u64 add2(u64 a, u64 b) {
    u64 d; asm("add.rn.f32x2 %0,%1,%2;" : "=l"(d) : "l"(a), "l"(b)); return d;
}
__device__ __forceinline__ float wsum(float v) {
#pragma unroll
    for (int o = 16; o; o >>= 1) v += __shfl_xor_sync(0xffffffffu, v, o);
    return v;
}
__device__ __forceinline__ u64 wsum2(u64 v) {
#pragma unroll
    for (int o = 16; o; o >>= 1)
        v = add2(v, __shfl_xor_sync(0xffffffffu, v, o));
    return v;
}

// ---- setup ------------------------------------------------------------------
__global__ void qae_setup(const float* __restrict__ w)
{
    int t = threadIdx.x;   // 1024 threads
    {
        int gi = (t ^ (t >> 1)) ^ ((t & 1) ? 0x300 : 0);
        float phA = 0.0f;
#pragma unroll
        for (int p = 0; p < 10; p++)
            phA += w[10 + 9 - p] * (((gi >> p) & 1) ? 0.5f : -0.5f);
        float c, s;
        sincosf(phA, &s, &c);
        d_phA[(t & 31) * 32 + (t >> 5)] = make_float2(c, s);
    }
    if (t < 20) {
        int st = t / 10, q = t % 10;
        float th = st ? (w[20 + q] + w[30 + q]) : w[q];
        float c, s; sincosf(0.5f * th, &s, &c);
        d_g[t] = make_float2(c, s);
    } else if (t < 26) {
        float c, s; sincosf(w[50 + (t - 20)], &s, &c);
        d_g[t] = make_float2(c, s);
    } else if (t < 33) {
        float c, s; sincosf(w[40 + (t - 26)], &s, &c);
        d_g[t] = make_float2(c, s);
    }
}

__global__ void __launch_bounds__(NT, 6)
qae13_kernel(const float* __restrict__ x,
             float* __restrict__ out,
             int B, int D)
{
    __shared__ u64    sbuf[SPB][34 * 32];   // 8704B/warp: float rows s34 / u64 rows s34
    __shared__ float2 sg[33];

    const int tid  = threadIdx.x;
    const int wid  = tid >> 5;
    const int lane = tid & 31;
    const int b    = blockIdx.x * SPB + wid;

    if (tid < 33) sg[tid] = d_g[tid];
    __syncthreads();
    if (b >= B) return;                 // warps independent from here

    float* bufr = (float*)sbuf[wid];    // stride-34 float view (T_A / C1)
    u64*   bufu = sbuf[wid];            // u64 view (T_A packed rows / T_B s34)

    // ---- load (L1, real, packed over qubit-9 pairs), 3-way -----------------
    u64 PA[16];
    float ss = 0.0f;
    const float* xrow = x + (size_t)b * D + lane * 32;
    if ((lane + 1) * 32 <= D) {         // full row
#pragma unroll
        for (int t = 0; t < 8; t++) {
            float4 v = *(const float4*)(xrow + t * 4);
            PA[2 * t]     = pk2(v.x, v.y);
            PA[2 * t + 1] = pk2(v.z, v.w);
            ss += v.x * v.x + v.y * v.y + v.z * v.z + v.w * v.w;
        }
    } else if (lane * 32 < D) {         // partial row
#pragma unroll
        for (int t = 0; t < 8; t++) {
            int idx = lane * 32 + t * 4;
            float4 v;
            v.x = (idx     < D) ? xrow[t * 4]     : 0.0f;
            v.y = (idx + 1 < D) ? xrow[t * 4 + 1] : 0.0f;
            v.z = (idx + 2 < D) ? xrow[t * 4 + 2] : 0.0f;
            v.w = (idx + 3 < D) ? xrow[t * 4 + 3] : 0.0f;
            PA[2 * t]     = pk2(v.x, v.y);
            PA[2 * t + 1] = pk2(v.z, v.w);
            ss += v.x * v.x + v.y * v.y + v.z * v.z + v.w * v.w;
        }
    } else {                            // fully out of range: zero fill
#pragma unroll
        for (int k = 0; k < 16; k++) PA[k] = 0ull;
    }
    ss = wsum(ss);
    float inv = 1.0f / fmaxf(sqrtf(ss), 1e-8f);

    // ---- stage A, qubits 9..5 (L1 reg bits; qubit 9 in-pack, norm folded) --
    {
        float2 g = sg[9];
        float ci = g.x * inv, si = g.y * inv;
        u64 cc = pk2(ci, ci), ns = pk2(-si, si);
#pragma unroll
        for (int k = 0; k < 16; k++) {
            u64 t = mul2(PA[k], cc);
            float lo, hi; upk2(PA[k], lo, hi);
            PA[k] = fma2(pk2(hi, lo), ns, t);
        }
    }
#pragma unroll
    for (int p = 1; p < 5; p++) {
        float2 g = sg[9 - p];
        u64 cc = pk2(g.x, g.x), sp = pk2(g.y, g.y), sn = pk2(-g.y, -g.y);
        int m = 1 << (p - 1);
#pragma unroll
        for (int k = 0; k < 16; k++) if (!(k & m)) {
            u64 a = PA[k], bb = PA[k | m];
            PA[k]     = fma2(bb, sn, mul2(a, cc));
            PA[k | m] = fma2(a, sp, mul2(bb, cc));
        }
    }

    // ---- T_A: L1 -> L0. float addr(i) = i[9:5]*34 + i[4:0] -----------------
#pragma unroll
    for (int k = 0; k < 16; k++) bufu[lane * 17 + k] = PA[k];
    __syncwarp();
    u64 PB[16];
#pragma unroll
    for (int k = 0; k < 16; k++)
        PB[k] = pk2(bufr[(2 * k) * 34 + lane], bufr[(2 * k + 1) * 34 + lane]);
    __syncwarp();

    // ---- stage A, qubits 4..0 (L0 reg bits; qubit 4 in-pack) ---------------
    {
        float2 g = sg[4];
        u64 cc = pk2(g.x, g.x), ns = pk2(-g.y, g.y);
#pragma unroll
        for (int k = 0; k < 16; k++) {
            u64 t = mul2(PB[k], cc);
            float lo, hi; upk2(PB[k], lo, hi);
            PB[k] = fma2(pk2(hi, lo), ns, t);
        }
    }
#pragma unroll
    for (int p = 1; p < 5; p++) {
        float2 g = sg[4 - p];
        u64 cc = pk2(g.x, g.x), sp = pk2(g.y, g.y), sn = pk2(-g.y, -g.y);
        int m = 1 << (p - 1);
#pragma unroll
        for (int k = 0; k < 16; k++) if (!(k & m)) {
            u64 a = PB[k], bb = PB[k | m];
            PB[k]     = fma2(bb, sn, mul2(a, cc));
            PB[k | m] = fma2(a, sp, mul2(bb, cc));
        }
    }

    // ---- C1: CNOT gather + PhA (store L0, read into L1, -> complex) --------
    u64 P[32];
    {
#pragma unroll
        for (int k = 0; k < 16; k++) {
            float lo, hi; upk2(PB[k], lo, hi);
            bufr[(2 * k) * 34 + lane]     = lo;
            bufr[(2 * k + 1) * 34 + lane] = hi;
        }
        __syncwarp();
        const u64* phA = (const u64*)d_phA;
#pragma unroll
        for (int j = 0; j < 32; j++) {  // output L1: lane=i[9:5], j=i[4:0]
            int i  = (lane << 5) | j;
            int gi = (i ^ (i >> 1)) ^ ((j & 1) ? 0x300 : 0);
            float r = bufr[(gi >> 5) * 34 + (gi & 31)];
            u64 ph = __ldg(&phA[j * 32 + lane]);
            P[j] = mul2(pk2(r, r), ph);
        }
        __syncwarp();
    }

    // ---- stage B, qubits 9..5 (L1 reg bits, complex f32x2) -----------------
#pragma unroll
    for (int bl = 0; bl < 5; bl++) {
        float2 g = sg[10 + 9 - bl];
        u64 cc = pk2(g.x, g.x), sp = pk2(g.y, g.y), sn = pk2(-g.y, -g.y);
        int m = 1 << bl;
#pragma unroll
        for (int j = 0; j < 32; j++) if (!(j & m)) {
            u64 a = P[j], bb = P[j | m];
            P[j]     = fma2(bb, sn, mul2(a, cc));
            P[j | m] = fma2(a, sp, mul2(bb, cc));
        }
    }

    // ---- T_B: L1 -> L0 (u64 rows stride 34; paired STS.128 writes) ---------
#pragma unroll
    for (int j = 0; j < 32; j += 2) {
        ulonglong2 v; v.x = P[j]; v.y = P[j + 1];
        *(ulonglong2*)&bufu[lane * 34 + j] = v;   // 16B-aligned (34*lane even)
    }
    __syncwarp();
#pragma unroll
    for (int j = 0; j < 32; j++) P[j] = bufu[j * 34 + lane];

    // ---- stage B, qubits 4..0 (L0 reg bits) --------------------------------
#pragma unroll
    for (int bl = 0; bl < 5; bl++) {
        float2 g = sg[10 + 4 - bl];
        u64 cc = pk2(g.x, g.x), sp = pk2(g.y, g.y), sn = pk2(-g.y, -g.y);
        int m = 1 << bl;
#pragma unroll
        for (int j = 0; j < 32; j++) if (!(j & m)) {
            u64 a = P[j], bb = P[j | m];
            P[j]     = fma2(bb, sn, mul2(a, cc));
            P[j | m] = fma2(a, sp, mul2(bb, cc));
        }
    }

    // ======= measurement with (PhB . Perm) pushed into the operators ========
    // L0: lane = j[4:0], reg r = j[9:5].
    const int lanepar = __popc(lane) & 1;
    const int lane4   = (lane >> 4) & 1;
    const int lane3   = (lane >> 3) & 1;

    // ---- Z: Walsh coefficients at masks M_p (reg part compile-time) --------
    float zA = 0, zB = 0, zC = 0, zD = 0, zE = 0;
#pragma unroll
    for (int r = 0; r < 32; r++) {
        u64 s = mul2(P[r], P[r]);
        float lo, hi; upk2(s, lo, hi);
        float nv = lo + hi;
        zA = (__popc(r & 0x0F) & 1) ? zA - nv : zA + nv;
        zB = (__popc(r & 0x18) & 1) ? zB - nv : zB + nv;
        zC = (__popc(r & 0x1C) & 1) ? zC - nv : zC + nv;
        zD = (__popc(r & 0x1E) & 1) ? zD - nv : zD + nv;
        zE = (__popc(r & 0x1F) & 1) ? zE - nv : zE + nv;
    }
    float zq[6];
    zq[0] = lanepar ? -zA : zA;
    zq[1] = zB; zq[2] = zC; zq[3] = zD; zq[4] = zE;
    zq[5] = lane4 ? -zE : zE;

    // ---- X/Y: q=0..3 (reg-pairs, Delta in r-bits), 4 phase buckets ---------
    float ReS[6], ImS[6];
    {
        const int DR[4] = {0x18, 0x0C, 0x06, 0x03};   // Delta (r part)
        const int KM[4] = {0x0F, 0x18, 0x1C, 0x1E};   // key mask (r part)
        const int BA[4] = {3, 2, 1, 0};               // r-bit of phase-bit a=p-1
#pragma unroll
        for (int q = 0; q < 4; q++) {
            const int dr = DR[q], low = dr & (-dr);
            u64 d0=0ull,d1=0ull,d2=0ull,d3=0ull, c0=0ull,c1=0ull,c2=0ull,c3=0ull;
#pragma unroll
            for (int r = 0; r < 32; r++) if (!(r & low)) {
                int k  = __popc(r & KM[q]) & 1;
                int ra = k ? (r ^ dr) : r;
                u64 a = P[ra], bb = P[ra ^ dr];
                float bl, bh; upk2(bb, bl, bh);
                u64 bs = pk2(bh, bl);
                int bkt = (((ra >> BA[q]) & 1) << 1) | ((ra >> (BA[q] + 1)) & 1);
                if      (bkt == 0) { d0 = fma2(a, bb, d0); c0 = fma2(a, bs, c0); }
                else if (bkt == 1) { d1 = fma2(a, bb, d1); c1 = fma2(a, bs, c1); }
                else if (bkt == 2) { d2 = fma2(a, bb, d2); c2 = fma2(a, bs, c2); }
                else               { d3 = fma2(a, bb, d3); c3 = fma2(a, bs, c3); }
            }
            float2 Eb = sg[26 + q], Ea = sg[26 + q + 1];
            float Re = 0.0f, Im = 0.0f;
            u64 AD[4] = {d0, d1, d2, d3}, AC[4] = {c0, c1, c2, c3};
#pragma unroll
            for (int t = 0; t < 4; t++) {
                int ja = (t >> 1) & 1, jb = t & 1;
                float sa = ja ? -Ea.y : Ea.y;
                float sb = jb ? -Eb.y : Eb.y;
                float cosd = Ea.x * Eb.x - sa * sb;
                float sind = sa * Eb.x + sb * Ea.x;
                float dl, dh, cl, ch; upk2(AD[t], dl, dh); upk2(AC[t], cl, ch);
                float Rb = dl + dh, Ib = cl - ch;
                Re += Rb * cosd - Ib * sind;
                Im += Rb * sind + Ib * cosd;
            }
            ReS[q] = Re;
            ImS[q] = (q == 0 && lanepar) ? -Im : Im;
        }
    }
    // ---- q=4: pairs (r, r^1) x (lane, lane^16); key = parity(r)=0 ----------
    {
        u64 dE=0ull, cE=0ull, dO=0ull, cO=0ull;
#pragma unroll
        for (int r = 0; r < 32; r++) if (!(__popc(r) & 1)) {
            u64 bb = __shfl_xor_sync(0xffffffffu, P[r ^ 1], 16);
            float bl, bh; upk2(bb, bl, bh);
            u64 bs = pk2(bh, bl);
            if (r & 1) { dO = fma2(P[r], bb, dO); cO = fma2(P[r], bs, cO); }
            else       { dE = fma2(P[r], bb, dE); cE = fma2(P[r], bs, cE); }
        }
        float dl, dh, cl, ch;
        upk2(dE, dl, dh); upk2(cE, cl, ch);
        float ReE = dl + dh, ImE = cl - ch;
        upk2(dO, dl, dh); upk2(cO, cl, ch);
        float ReO = dl + dh, ImO = cl - ch;
        float2 E5 = sg[30];
        float Re = (ReE * E5.x - ImE * E5.y) + (ReO * E5.x + ImO * E5.y);
        float Im = (ReE * E5.y + ImE * E5.x) + (ImO * E5.x - ReO * E5.y);
        float2 E4 = sg[31];
        float c4 = E4.x, s4 = lane4 ? -E4.y : E4.y;
        ReS[4] = Re * c4 - Im * s4;
        ImS[4] = Re * s4 + Im * c4;
    }
    // ---- q=5: pairs (lane, lane^24); key = parity(r)^lane4 -----------------
    {
        u64 dE=0ull, cE=0ull, dO=0ull, cO=0ull;
#pragma unroll
        for (int r = 0; r < 32; r++) {
            u64 bb = __shfl_xor_sync(0xffffffffu, P[r], 24);
            float bl, bh; upk2(bb, bl, bh);
            u64 bs = pk2(bh, bl);
            if (__popc(r) & 1) { dO = fma2(P[r], bb, dO); cO = fma2(P[r], bs, cO); }
            else               { dE = fma2(P[r], bb, dE); cE = fma2(P[r], bs, cE); }
        }
        u64 ad = lane4 ? dO : dE;
        u64 ac = lane4 ? cO : cE;
        float dl, dh, cl, ch; upk2(ad, dl, dh); upk2(ac, cl, ch);
        float Re = dl + dh, Im = cl - ch;
        float2 E3 = sg[32];
        float2 E4 = sg[31];
        float s3 = lane3 ? -E3.y : E3.y;
        float s4 = lane4 ? -E4.y : E4.y;
        float cosd = E3.x * E4.x - s3 * s4;
        float sind = s3 * E4.x + s4 * E3.x;
        ReS[5] = Re * cosd - Im * sind;
        ImS[5] = Re * sind + Im * cosd;
    }

    // ---- packed final reductions (9 u64 wsums instead of 18 scalar) --------
    u64 RI[6], ZP[3];
#pragma unroll
    for (int q = 0; q < 6; q++) RI[q] = wsum2(pk2(ReS[q], ImS[q]));
#pragma unroll
    for (int k = 0; k < 3; k++) ZP[k] = wsum2(pk2(zq[2 * k], zq[2 * k + 1]));

    if (lane == 0) {
        float* o = out + (size_t)b * 18;
        float zz[6];
#pragma unroll
        for (int k = 0; k < 3; k++) upk2(ZP[k], zz[2 * k], zz[2 * k + 1]);
#pragma unroll
        for (int q = 0; q < 6; q++) {
            float re, im; upk2(RI[q], re, im);
            float X = 2.0f * re, Y = 2.0f * im;
            float2 gc = sg[20 + q];
            o[q]      = gc.x * X + gc.y * zz[q];
            o[6 + q]  = Y;
            o[12 + q] = gc.x * zz[q] - gc.y * X;
        }
    }
}

extern "C" void kernel_launch(void* const* d_in, const int* in_sizes, int n_in,
                              void* d_out, int out_size)
{
    int ix = 0, iw = 1;
    if (n_in >= 2 && in_sizes[0] < in_sizes[1]) { ix = 1; iw = 0; }
    const float* x = (const float*)d_in[ix];
    const float* w = (const float*)d_in[iw];
    float* out = (float*)d_out;

    int B = out_size / 18;
    int D = (B > 0) ? (in_sizes[ix] / B) : 0;

    qae_setup<<<1, 1024>>>(w);
    int grid = (B + SPB - 1) / SPB;
    qae13_kernel<<<grid, NT>>>(x, out, B, D);
}